// round 12
// baseline (speedup 1.0000x reference)
#include <cuda_runtime.h>
#include <cuda_fp16.h>
#include <cstdint>
#include <cstddef>

#define DIM  1024
#define NTOK 16384
#define NEXP 8

// ------------------- device scratch (static; no runtime allocs) -------------------
__device__ int    g_cnt[NEXP];                      // zero-init; self-reset by gemm
__device__ int    g_done;                           // gemm completion ticket
__device__ int    g_tok[NEXP * NTOK];
__device__ float  g_gate[NEXP * NTOK];
__device__ __half g_xh[NTOK * DIM];                 // x in fp16 (32 MB) — written by router
__device__ __half g_wh[NEXP * DIM * DIM];           // W in fp16 (16 MB)

// ------------------- helpers -------------------
__device__ __forceinline__ uint32_t smem_u32(const void* p) {
    uint32_t a;
    asm("{ .reg .u64 t; cvta.to.shared.u64 t, %1; cvt.u32.u64 %0, t; }" : "=r"(a) : "l"(p));
    return a;
}
__device__ __forceinline__ void cp16(uint32_t dst, const void* src) {
    asm volatile("cp.async.cg.shared.global [%0], [%1], 16;" :: "r"(dst), "l"(src) : "memory");
}
__device__ __forceinline__ uint32_t swz(uint32_t o) { return o ^ ((o >> 3) & 0x70); }

__device__ __forceinline__ void ldsm4(uint32_t& r0, uint32_t& r1, uint32_t& r2, uint32_t& r3,
                                      uint32_t addr) {
    asm volatile("ldmatrix.sync.aligned.m8n8.x4.shared.b16 {%0,%1,%2,%3}, [%4];"
                 : "=r"(r0), "=r"(r1), "=r"(r2), "=r"(r3) : "r"(addr));
}
__device__ __forceinline__ void mma_f16(float* c, const uint32_t* a, const uint32_t* b) {
    asm volatile(
        "mma.sync.aligned.m16n8k16.row.col.f32.f16.f16.f32 "
        "{%0,%1,%2,%3}, {%4,%5,%6,%7}, {%8,%9}, {%0,%1,%2,%3};"
        : "+f"(c[0]), "+f"(c[1]), "+f"(c[2]), "+f"(c[3])
        : "r"(a[0]), "r"(a[1]), "r"(a[2]), "r"(a[3]), "r"(b[0]), "r"(b[1]));
}
__device__ __forceinline__ void red2(float* addr, float x, float y) {
    asm volatile("red.global.add.v2.f32 [%0], {%1, %2};"
                 :: "l"(addr), "f"(x), "f"(y) : "memory");
}

// ------------------- kernel A: fused prep (W fp16 + out zero) & router (+x fp16) --------
constexpr int PREP_BLOCKS   = 1480;
constexpr int ROUTER_BLOCKS = NTOK / 8;            // 2048
constexpr int FUSED_BLOCKS  = PREP_BLOCKS + ROUTER_BLOCKS;

__global__ void __launch_bounds__(256) fused_prep_router(
    const float* __restrict__ x, const float* __restrict__ rw,
    const float* __restrict__ rb, const float4* __restrict__ ew,
    float4* __restrict__ out)
{
    const int tid = threadIdx.x;
    if (blockIdx.x < PREP_BLOCKS) {
        const int stride = PREP_BLOCKS * 256;
        const int t0 = blockIdx.x * 256 + tid;
        uint2* wh = (uint2*)g_wh;
        for (int i = t0; i < NEXP * DIM * DIM / 4; i += stride) {
            float4 v = ew[i];
            __half2 lo = __floats2half2_rn(v.x, v.y);
            __half2 hi = __floats2half2_rn(v.z, v.w);
            uint2 o;
            o.x = *(uint32_t*)&lo; o.y = *(uint32_t*)&hi;
            wh[i] = o;
        }
        const float4 z = make_float4(0.f, 0.f, 0.f, 0.f);
        for (int i = t0; i < NTOK * DIM / 4; i += stride) out[i] = z;
        return;
    }
    // ---- router: warp per token; also converts its x row to fp16 ----
    __shared__ float4 rw_sm[NEXP * DIM / 4];   // 32 KB
    const int lane = tid & 31, wid = tid >> 5;
    const float4* rw4 = (const float4*)rw;
#pragma unroll
    for (int j = 0; j < NEXP * DIM / 4 / 256; j++)
        rw_sm[tid + 256 * j] = rw4[tid + 256 * j];
    __syncthreads();

    const int n = (blockIdx.x - PREP_BLOCKS) * 8 + wid;
    const float4* xr = (const float4*)(x + (size_t)n * DIM);
    uint2* xh_row = (uint2*)(g_xh + (size_t)n * DIM);
    float acc[NEXP];
#pragma unroll
    for (int e = 0; e < NEXP; e++) acc[e] = 0.f;
#pragma unroll
    for (int i = 0; i < 8; i++) {
        float4 xv = xr[lane + 32 * i];
        __half2 lo = __floats2half2_rn(xv.x, xv.y);
        __half2 hi = __floats2half2_rn(xv.z, xv.w);
        uint2 o;
        o.x = *(uint32_t*)&lo; o.y = *(uint32_t*)&hi;
        xh_row[lane + 32 * i] = o;
#pragma unroll
        for (int e = 0; e < NEXP; e++) {
            float4 w = rw_sm[e * 256 + lane + 32 * i];
            acc[e] += xv.x * w.x + xv.y * w.y + xv.z * w.z + xv.w * w.w;
        }
    }
#pragma unroll
    for (int e = 0; e < NEXP; e++)
#pragma unroll
        for (int o = 16; o; o >>= 1) acc[e] += __shfl_xor_sync(0xffffffffu, acc[e], o);

    if (lane == 0) {
        float logit[NEXP];
#pragma unroll
        for (int e = 0; e < NEXP; e++) logit[e] = acc[e] + rb[e];
        int e0 = 0; float l0 = logit[0];
#pragma unroll
        for (int e = 1; e < NEXP; e++) if (logit[e] > l0) { l0 = logit[e]; e0 = e; }
        int e1 = -1; float l1 = -1e30f;
#pragma unroll
        for (int e = 0; e < NEXP; e++)
            if (e != e0 && logit[e] > l1) { l1 = logit[e]; e1 = e; }
        float g0 = 1.f / (1.f + __expf(l1 - l0));
        float g1 = 1.f - g0;
        int p0 = atomicAdd(&g_cnt[e0], 1);
        g_tok[e0 * NTOK + p0]  = n;
        g_gate[e0 * NTOK + p0] = g0;
        int p1 = atomicAdd(&g_cnt[e1], 1);
        g_tok[e1 * NTOK + p1]  = n;
        g_gate[e1 * NTOK + p1] = g1;
    }
}

// ------------------- kernel B: grouped gather-GEMM, software-pipelined -------------------
// BM=128, BN=128, BK=64 halves, 3-stage cp.async, 128 threads.
// 4 warps in 2x2; warp tile 64x64; A frags double-buffered, B single-buffered
// (register relief vs R11's 255-reg spill). 2 CTAs/SM. Self-resets g_cnt.
constexpr int BM = 128, BN = 128, NSTAGE = 3;
constexpr int KT = DIM / 64;                       // 16
constexpr int GRID_X = DIM / BN;                   // 8
constexpr int GRID_Y = NTOK / BM;                  // 128
constexpr int TOTAL_CTAS = GRID_X * GRID_Y * NEXP; // 8192

constexpr uint32_t SM_TOK  = 0;                    // 128 ints
constexpr uint32_t SM_GATE = 512;                  // 128 floats
constexpr uint32_t SM_BIAS = 1024;                 // 128 floats
constexpr uint32_t SM_STG  = 2048;
constexpr uint32_t SLOT_SZ = 32768;                // A 16KB + B 16KB
constexpr uint32_t SMEM_TOTAL = SM_STG + NSTAGE * SLOT_SZ;   // 100352 B

__global__ void __launch_bounds__(128, 2) gemm_kernel(const float* __restrict__ eb,
                                                      float* __restrict__ out) {
    extern __shared__ char smem[];
    const int e  = blockIdx.z;
    const int mt = blockIdx.y;
    const int nt = blockIdx.x;
    const int cnt = g_cnt[e];
    const int tid = threadIdx.x, wid = tid >> 5, lane = tid & 31;

    if (mt * BM < cnt) {
        const uint32_t sb = smem_u32(smem);
        int*   tok_sm  = (int*)(smem + SM_TOK);
        float* gate_sm = (float*)(smem + SM_GATE);
        float* bias_sm = (float*)(smem + SM_BIAS);

        {
            int r = mt * BM + tid;
            bool v = r < cnt;
            tok_sm[tid]  = v ? g_tok[e * NTOK + r] : 0;
            gate_sm[tid] = v ? g_gate[e * NTOK + r] : 0.f;
            bias_sm[tid] = eb[e * DIM + nt * BN + tid];
        }
        __syncthreads();

        const __half* wh_e = g_wh + (size_t)e * DIM * DIM;

        auto load_stage = [&](int slot, int kt) {
            uint32_t aB = sb + SM_STG + slot * SLOT_SZ;
            uint32_t bB = aB + 16384;
#pragma unroll
            for (int j = 0; j < 8; j++) {
                int idx = tid + 128 * j, row = idx >> 3, ch = idx & 7;
                int tok = tok_sm[row] & (NTOK - 1);
                cp16(aB + swz(row * 128 + ch * 16),
                     g_xh + ((size_t)tok << 10) + (kt << 6) + (ch << 3));
            }
#pragma unroll
            for (int j = 0; j < 8; j++) {
                int idx = tid + 128 * j, row = idx >> 3, ch = idx & 7;
                cp16(bB + swz(row * 128 + ch * 16),
                     wh_e + (((size_t)(nt * BN + row)) << 10) + (kt << 6) + (ch << 3));
            }
            asm volatile("cp.async.commit_group;" ::: "memory");
        };

        load_stage(0, 0);
        load_stage(1, 1);
        load_stage(2, 2);

        const int wm = wid >> 1, wn = wid & 1;      // 2 x 2 warp grid, tile 64x64
        const int aRow  = lane & 15,            aHalf = lane >> 4;
        const int bRow  = (lane & 7) + ((lane >> 4) << 3);
        const int bHalf = (lane >> 3) & 1;
        const int gID = lane >> 2, tig = lane & 3;

        float acc[4][8][4];
#pragma unroll
        for (int mi = 0; mi < 4; mi++)
#pragma unroll
            for (int ni = 0; ni < 8; ni++)
#pragma unroll
                for (int q = 0; q < 4; q++) acc[mi][ni][q] = 0.f;

        uint32_t afr[2][4][4];     // A: double-buffered
        uint32_t bfr[8][2];        // B: single-buffered (reg relief)

        auto ld_a = [&](int buf, uint32_t aB, int ks) {
#pragma unroll
            for (int mi = 0; mi < 4; mi++) {
                int row = wm * 64 + mi * 16 + aRow;
                ldsm4(afr[buf][mi][0], afr[buf][mi][1], afr[buf][mi][2], afr[buf][mi][3],
                      aB + swz(row * 128 + ks * 32 + aHalf * 16));
            }
        };
        auto ld_b = [&](uint32_t bB, int ks) {
#pragma unroll
            for (int p = 0; p < 4; p++) {
                int row = wn * 64 + p * 16 + bRow;
                ldsm4(bfr[2 * p][0], bfr[2 * p][1], bfr[2 * p + 1][0], bfr[2 * p + 1][1],
                      bB + swz(row * 128 + ks * 32 + bHalf * 16));
            }
        };
        auto do_mma = [&](int abuf) {
#pragma unroll
            for (int mi = 0; mi < 4; mi++)
#pragma unroll
                for (int ni = 0; ni < 8; ni++)
                    mma_f16(acc[mi][ni], afr[abuf][mi], bfr[ni]);
        };

        // prime: slot0 ready, fragments <- (kt0, ks0)
        asm volatile("cp.async.wait_group 2;" ::: "memory");
        __syncthreads();
        ld_a(0, sb + SM_STG, 0);
        ld_b(sb + SM_STG + 16384, 0);

        for (int kt = 0; kt < KT; kt++) {
            const uint32_t aB = sb + SM_STG + (kt % NSTAGE) * SLOT_SZ;
            const uint32_t bB = aB + 16384;
#pragma unroll
            for (int ks = 0; ks < 4; ks++) {
                const int cur = ks & 1, nx = cur ^ 1;
                if (ks < 3) {
                    ld_a(nx, aB, ks + 1);          // prefetch A(ks+1)
                    do_mma(cur);                    // mma (kt, ks); B consumed at issue
                    ld_b(bB, ks + 1);              // reload B(ks+1) behind the batch
                } else {
                    if (kt < KT - 1) {
                        // stage boundary: slot kt+1 must be ready
                        asm volatile("cp.async.wait_group 1;" ::: "memory");
                        __syncthreads();
                        int n3 = kt + 3;
                        if (n3 < KT) load_stage(n3 % NSTAGE, n3);
                        else asm volatile("cp.async.commit_group;" ::: "memory");
                        const uint32_t aN = sb + SM_STG + ((kt + 1) % NSTAGE) * SLOT_SZ;
                        ld_a(nx, aN, 0);           // prefetch (kt+1, ks0)
                        do_mma(cur);                // deferred mma hides post-bar LDSM
                        ld_b(aN + 16384, 0);
                    } else {
                        do_mma(cur);
                    }
                }
            }
        }

        // ---- epilogue: red.global.add of gate*(acc+bias) into out ----
#pragma unroll
        for (int mi = 0; mi < 4; mi++) {
#pragma unroll
            for (int half = 0; half < 2; half++) {
                int lr = wm * 64 + mi * 16 + gID + half * 8;
                if (mt * BM + lr < cnt) {
                    int   tr = tok_sm[lr] & (NTOK - 1);
                    float g  = gate_sm[lr];
                    float* dst = out + ((size_t)tr << 10) + nt * BN;
#pragma unroll
                    for (int ni = 0; ni < 8; ni++) {
                        int c = wn * 64 + ni * 8 + tig * 2;
                        float vx = g * (acc[mi][ni][half * 2 + 0] + bias_sm[c]);
                        float vy = g * (acc[mi][ni][half * 2 + 1] + bias_sm[c + 1]);
                        red2(dst + c, vx, vy);
                    }
                }
            }
        }
    }

    // ---- completion ticket: last CTA resets counters for the next replay ----
    if (tid == 0) {
        int d = atomicAdd(&g_done, 1);
        if (d == TOTAL_CTAS - 1) {
#pragma unroll
            for (int i = 0; i < NEXP; i++) g_cnt[i] = 0;
            atomicExch(&g_done, 0);
        }
    }
}

// ------------------- launch -------------------
extern "C" void kernel_launch(void* const* d_in, const int* in_sizes, int n_in,
                              void* d_out, int out_size) {
    const float* x  = (const float*)d_in[0];
    const float* rw = (const float*)d_in[1];
    const float* rb = (const float*)d_in[2];
    const float* ew = (const float*)d_in[3];
    const float* eb = (const float*)d_in[4];

    cudaFuncSetAttribute(gemm_kernel, cudaFuncAttributeMaxDynamicSharedMemorySize,
                         (int)SMEM_TOTAL);

    fused_prep_router<<<FUSED_BLOCKS, 256>>>(x, rw, rb,
                                             (const float4*)ew, (float4*)d_out);  // idx 0
    gemm_kernel<<<dim3(GRID_X, GRID_Y, NEXP), 128, SMEM_TOTAL>>>(
        eb, (float*)d_out);                                     // idx 1 -> profiled (#4)
}

// round 13
// speedup vs baseline: 1.0283x; 1.0283x over previous
#include <cuda_runtime.h>
#include <cuda_fp16.h>
#include <cstdint>
#include <cstddef>

#define DIM  1024
#define NTOK 16384
#define NEXP 8

// ------------------- device scratch (static; no runtime allocs) -------------------
__device__ int    g_cnt[NEXP];                      // zero-init; self-reset by gemm
__device__ int    g_widx;                           // work ticket
__device__ int    g_done;                           // completion ticket
__device__ int    g_tok[NEXP * NTOK];
__device__ float  g_gate[NEXP * NTOK];
__device__ __half g_xh[NTOK * DIM];                 // x in fp16 — written by router
__device__ __half g_wh[NEXP * DIM * DIM];           // W in fp16

// ------------------- helpers -------------------
__device__ __forceinline__ uint32_t smem_u32(const void* p) {
    uint32_t a;
    asm("{ .reg .u64 t; cvta.to.shared.u64 t, %1; cvt.u32.u64 %0, t; }" : "=r"(a) : "l"(p));
    return a;
}
__device__ __forceinline__ void cp16(uint32_t dst, const void* src) {
    asm volatile("cp.async.cg.shared.global [%0], [%1], 16;" :: "r"(dst), "l"(src) : "memory");
}
__device__ __forceinline__ uint32_t swz(uint32_t o) { return o ^ ((o >> 3) & 0x70); }

__device__ __forceinline__ void ldsm4(uint32_t& r0, uint32_t& r1, uint32_t& r2, uint32_t& r3,
                                      uint32_t addr) {
    asm volatile("ldmatrix.sync.aligned.m8n8.x4.shared.b16 {%0,%1,%2,%3}, [%4];"
                 : "=r"(r0), "=r"(r1), "=r"(r2), "=r"(r3) : "r"(addr));
}
__device__ __forceinline__ void mma_f16(float* c, const uint32_t* a, const uint32_t* b) {
    asm volatile(
        "mma.sync.aligned.m16n8k16.row.col.f32.f16.f16.f32 "
        "{%0,%1,%2,%3}, {%4,%5,%6,%7}, {%8,%9}, {%0,%1,%2,%3};"
        : "+f"(c[0]), "+f"(c[1]), "+f"(c[2]), "+f"(c[3])
        : "r"(a[0]), "r"(a[1]), "r"(a[2]), "r"(a[3]), "r"(b[0]), "r"(b[1]));
}
__device__ __forceinline__ void red4(float* addr, float x, float y, float z, float w) {
    asm volatile("red.global.add.v4.f32 [%0], {%1, %2, %3, %4};"
                 :: "l"(addr), "f"(x), "f"(y), "f"(z), "f"(w) : "memory");
}

// ------------------- kernel A: fused prep (W fp16 + out zero) & router (+x fp16) --------
constexpr int PREP_BLOCKS   = 1480;
constexpr int ROUTER_BLOCKS = NTOK / 8;            // 2048
constexpr int FUSED_BLOCKS  = PREP_BLOCKS + ROUTER_BLOCKS;

__global__ void __launch_bounds__(256) fused_prep_router(
    const float* __restrict__ x, const float* __restrict__ rw,
    const float* __restrict__ rb, const float4* __restrict__ ew,
    float4* __restrict__ out)
{
    const int tid = threadIdx.x;
    if (blockIdx.x < PREP_BLOCKS) {
        const int stride = PREP_BLOCKS * 256;
        const int t0 = blockIdx.x * 256 + tid;
        uint2* wh = (uint2*)g_wh;
        for (int i = t0; i < NEXP * DIM * DIM / 4; i += stride) {
            float4 v = ew[i];
            __half2 lo = __floats2half2_rn(v.x, v.y);
            __half2 hi = __floats2half2_rn(v.z, v.w);
            uint2 o;
            o.x = *(uint32_t*)&lo; o.y = *(uint32_t*)&hi;
            wh[i] = o;
        }
        const float4 z = make_float4(0.f, 0.f, 0.f, 0.f);
        for (int i = t0; i < NTOK * DIM / 4; i += stride) out[i] = z;
        return;
    }
    // ---- router: warp per token; also converts its x row to fp16 ----
    __shared__ float4 rw_sm[NEXP * DIM / 4];   // 32 KB
    const int lane = tid & 31, wid = tid >> 5;
    const float4* rw4 = (const float4*)rw;
#pragma unroll
    for (int j = 0; j < NEXP * DIM / 4 / 256; j++)
        rw_sm[tid + 256 * j] = rw4[tid + 256 * j];
    __syncthreads();

    const int n = (blockIdx.x - PREP_BLOCKS) * 8 + wid;
    const float4* xr = (const float4*)(x + (size_t)n * DIM);
    uint2* xh_row = (uint2*)(g_xh + (size_t)n * DIM);
    float acc[NEXP];
#pragma unroll
    for (int e = 0; e < NEXP; e++) acc[e] = 0.f;
#pragma unroll
    for (int i = 0; i < 8; i++) {
        float4 xv = xr[lane + 32 * i];
        __half2 lo = __floats2half2_rn(xv.x, xv.y);
        __half2 hi = __floats2half2_rn(xv.z, xv.w);
        uint2 o;
        o.x = *(uint32_t*)&lo; o.y = *(uint32_t*)&hi;
        xh_row[lane + 32 * i] = o;
#pragma unroll
        for (int e = 0; e < NEXP; e++) {
            float4 w = rw_sm[e * 256 + lane + 32 * i];
            acc[e] += xv.x * w.x + xv.y * w.y + xv.z * w.z + xv.w * w.w;
        }
    }
#pragma unroll
    for (int e = 0; e < NEXP; e++)
#pragma unroll
        for (int o = 16; o; o >>= 1) acc[e] += __shfl_xor_sync(0xffffffffu, acc[e], o);

    if (lane == 0) {
        float logit[NEXP];
#pragma unroll
        for (int e = 0; e < NEXP; e++) logit[e] = acc[e] + rb[e];
        int e0 = 0; float l0 = logit[0];
#pragma unroll
        for (int e = 1; e < NEXP; e++) if (logit[e] > l0) { l0 = logit[e]; e0 = e; }
        int e1 = -1; float l1 = -1e30f;
#pragma unroll
        for (int e = 0; e < NEXP; e++)
            if (e != e0 && logit[e] > l1) { l1 = logit[e]; e1 = e; }
        float g0 = 1.f / (1.f + __expf(l1 - l0));
        float g1 = 1.f - g0;
        int p0 = atomicAdd(&g_cnt[e0], 1);
        g_tok[e0 * NTOK + p0]  = n;
        g_gate[e0 * NTOK + p0] = g0;
        int p1 = atomicAdd(&g_cnt[e1], 1);
        g_tok[e1 * NTOK + p1]  = n;
        g_gate[e1 * NTOK + p1] = g1;
    }
}

// ------------------- kernel B: persistent grouped gather-GEMM -------------------
// BM=128, BN=128, BK=64 halves, 3-stage cp.async, 128 threads, 2 CTAs/SM.
// Persistent ticket scheduler; next-tile prologue prefetched under epilogue;
// epilogue uses red.global.add.v4 via lane-pair shuffle.
constexpr int BM = 128, BN = 128, NSTAGE = 3;
constexpr int KT = DIM / 64;                       // 16
constexpr int GRID_CTAS = 304;                     // 2 per SM (152 SMs)

constexpr uint32_t SM_ITEM = 0;                    // 1 int
constexpr uint32_t SM_OFFS = 16;                   // 9 ints
constexpr uint32_t SM_TOK  = 64;                   // 2 x 128 ints
constexpr uint32_t SM_GATE = SM_TOK + 1024;        // 2 x 128 floats
constexpr uint32_t SM_BIAS = SM_GATE + 1024;       // 2 x 128 floats
constexpr uint32_t SM_STG  = 4096;
constexpr uint32_t SLOT_SZ = 32768;                // A 16KB + B 16KB
constexpr uint32_t SMEM_TOTAL = SM_STG + NSTAGE * SLOT_SZ;   // 102400 B

__global__ void __launch_bounds__(128, 2) gemm_kernel(const float* __restrict__ eb,
                                                      float* __restrict__ out) {
    extern __shared__ char smem[];
    const int tid = threadIdx.x, wid = tid >> 5, lane = tid & 31;
    const uint32_t sb = smem_u32(smem);
    int*   item_sm = (int*)(smem + SM_ITEM);
    int*   offs_sm = (int*)(smem + SM_OFFS);
    int*   tok_sm  = (int*)(smem + SM_TOK);
    float* gate_sm = (float*)(smem + SM_GATE);
    float* bias_sm = (float*)(smem + SM_BIAS);

    if (tid == 0) {
        int s = 0;
#pragma unroll
        for (int e = 0; e < NEXP; e++) {
            offs_sm[e] = s;
            s += ((g_cnt[e] + BM - 1) >> 7) * (DIM / BN);
        }
        offs_sm[NEXP] = s;
        item_sm[0] = atomicAdd(&g_widx, 1);
    }
    __syncthreads();
    const int nwork = offs_sm[NEXP];

    auto decode = [&](int i, int& e, int& mt, int& nt) {
        int ee = 0;
        while (ee < NEXP - 1 && i >= offs_sm[ee + 1]) ee++;
        e = ee;
        int r = i - offs_sm[ee];
        mt = r >> 3;
        nt = r & 7;
    };
    auto load_meta = [&](int buf, int e, int mt, int nt, int cnt) {
        int r = mt * BM + tid;
        bool v = r < cnt;
        tok_sm[buf * 128 + tid]  = v ? g_tok[e * NTOK + r] : 0;
        gate_sm[buf * 128 + tid] = v ? g_gate[e * NTOK + r] : 0.f;
        bias_sm[buf * 128 + tid] = eb[e * DIM + nt * BN + tid];
    };
    auto load_stage = [&](int slot, int kt, const int* tokp, const __half* wh_e, int nt_) {
        uint32_t aB = sb + SM_STG + slot * SLOT_SZ;
        uint32_t bB = aB + 16384;
#pragma unroll
        for (int j = 0; j < 8; j++) {
            int idx = tid + 128 * j, row = idx >> 3, ch = idx & 7;
            int tok = tokp[row] & (NTOK - 1);
            cp16(aB + swz(row * 128 + ch * 16),
                 g_xh + ((size_t)tok << 10) + (kt << 6) + (ch << 3));
        }
#pragma unroll
        for (int j = 0; j < 8; j++) {
            int idx = tid + 128 * j, row = idx >> 3, ch = idx & 7;
            cp16(bB + swz(row * 128 + ch * 16),
                 wh_e + (((size_t)(nt_ * BN + row)) << 10) + (kt << 6) + (ch << 3));
        }
        asm volatile("cp.async.commit_group;" ::: "memory");
    };

    const int wm = wid >> 1, wn = wid & 1;          // 2 x 2 warp grid, tile 64x64
    const int aRow  = lane & 15,            aHalf = lane >> 4;
    const int bRow  = (lane & 7) + ((lane >> 4) << 3);
    const int bHalf = (lane >> 3) & 1;
    const int gID = lane >> 2, tig = lane & 3;
    const int odd = lane & 1;

    // ---- first tile: ticket + meta + prologue stages ----
    int item = item_sm[0];
    bool have = item < nwork;
    int e = 0, mt = 0, nt = 0, cnt = 0, buf = 0;
    if (have) {
        decode(item, e, mt, nt);
        cnt = g_cnt[e];
        load_meta(0, e, mt, nt, cnt);
    }
    __syncthreads();
    if (have) {
        const __half* whe = g_wh + (size_t)e * DIM * DIM;
        load_stage(0, 0, tok_sm, whe, nt);
        load_stage(1, 1, tok_sm, whe, nt);
        load_stage(2, 2, tok_sm, whe, nt);
    }

    float acc[4][8][4];
    uint32_t afr[2][4][4];
    uint32_t bfr[8][2];

    auto ld_a = [&](int b2, uint32_t aB, int ks) {
#pragma unroll
        for (int mi = 0; mi < 4; mi++) {
            int row = wm * 64 + mi * 16 + aRow;
            ldsm4(afr[b2][mi][0], afr[b2][mi][1], afr[b2][mi][2], afr[b2][mi][3],
                  aB + swz(row * 128 + ks * 32 + aHalf * 16));
        }
    };
    auto ld_b = [&](uint32_t bB, int ks) {
#pragma unroll
        for (int p = 0; p < 4; p++) {
            int row = wn * 64 + p * 16 + bRow;
            ldsm4(bfr[2 * p][0], bfr[2 * p][1], bfr[2 * p + 1][0], bfr[2 * p + 1][1],
                  bB + swz(row * 128 + ks * 32 + bHalf * 16));
        }
    };
    auto do_mma = [&](int abuf) {
#pragma unroll
        for (int mi = 0; mi < 4; mi++)
#pragma unroll
            for (int ni = 0; ni < 8; ni++)
                mma_f16(acc[mi][ni], afr[abuf][mi], bfr[ni]);
    };

    while (have) {
        const int* tokc = tok_sm + buf * 128;
        const __half* whe = g_wh + (size_t)e * DIM * DIM;
#pragma unroll
        for (int mi = 0; mi < 4; mi++)
#pragma unroll
            for (int ni = 0; ni < 8; ni++)
#pragma unroll
                for (int q = 0; q < 4; q++) acc[mi][ni][q] = 0.f;

        // prime this tile
        asm volatile("cp.async.wait_group 2;" ::: "memory");
        __syncthreads();
        ld_a(0, sb + SM_STG, 0);
        ld_b(sb + SM_STG + 16384, 0);

        for (int kt = 0; kt < KT; kt++) {
            const uint32_t aB = sb + SM_STG + (kt % NSTAGE) * SLOT_SZ;
            const uint32_t bB = aB + 16384;
#pragma unroll
            for (int ks = 0; ks < 4; ks++) {
                const int cur = ks & 1, nx = cur ^ 1;
                if (ks < 3) {
                    ld_a(nx, aB, ks + 1);
                    do_mma(cur);
                    ld_b(bB, ks + 1);
                } else {
                    if (kt < KT - 1) {
                        asm volatile("cp.async.wait_group 1;" ::: "memory");
                        __syncthreads();
                        int n3 = kt + 3;
                        if (n3 < KT) load_stage(n3 % NSTAGE, n3, tokc, whe, nt);
                        else asm volatile("cp.async.commit_group;" ::: "memory");
                        const uint32_t aN = sb + SM_STG + ((kt + 1) % NSTAGE) * SLOT_SZ;
                        ld_a(nx, aN, 0);
                        do_mma(cur);
                        ld_b(aN + 16384, 0);
                    } else {
                        do_mma(cur);
                    }
                }
            }
        }

        // ---- fetch next ticket + meta, issue next prologue (hides under epilogue) ----
        if (tid == 0) item_sm[0] = atomicAdd(&g_widx, 1);
        __syncthreads();
        int item2 = item_sm[0];
        bool have2 = item2 < nwork;
        int e2 = 0, mt2 = 0, nt2 = 0, cnt2 = 0;
        const int nbuf = buf ^ 1;
        if (have2) {
            decode(item2, e2, mt2, nt2);
            cnt2 = g_cnt[e2];
            load_meta(nbuf, e2, mt2, nt2, cnt2);
        }
        __syncthreads();
        if (have2) {
            const __half* whe2 = g_wh + (size_t)e2 * DIM * DIM;
            const int* tokn = tok_sm + nbuf * 128;
            load_stage(0, 0, tokn, whe2, nt2);
            load_stage(1, 1, tokn, whe2, nt2);
            load_stage(2, 2, tokn, whe2, nt2);
        }

        // ---- epilogue: red4 of gate*(acc+bias), lane-pair shuffle packing ----
        {
            const float* gatec = gate_sm + buf * 128;
            const float* biasc = bias_sm + buf * 128;
#pragma unroll
            for (int mi = 0; mi < 4; mi++) {
                int lr = wm * 64 + mi * 16 + gID + (odd ? 8 : 0);
                bool valid = (mt * BM + lr) < cnt;
                int   tr = tokc[lr] & (NTOK - 1);
                float g  = gatec[lr];
                float* dst = out + ((size_t)tr << 10) + nt * BN;
#pragma unroll
                for (int ni = 0; ni < 8; ni++) {
                    float a0 = acc[mi][ni][0], a1 = acc[mi][ni][1];
                    float a2 = acc[mi][ni][2], a3 = acc[mi][ni][3];
                    float r0 = __shfl_xor_sync(0xffffffffu, a0, 1);
                    float r1 = __shfl_xor_sync(0xffffffffu, a1, 1);
                    float r2 = __shfl_xor_sync(0xffffffffu, a2, 1);
                    float r3 = __shfl_xor_sync(0xffffffffu, a3, 1);
                    float v0, v1, v2, v3;
                    if (!odd) { v0 = a0; v1 = a1; v2 = r0; v3 = r1; }   // row half0
                    else      { v0 = r2; v1 = r3; v2 = a2; v3 = a3; }   // row half1
                    int c = wn * 64 + ni * 8 + (tig & 2) * 2;
                    if (valid) {
                        v0 = g * (v0 + biasc[c]);
                        v1 = g * (v1 + biasc[c + 1]);
                        v2 = g * (v2 + biasc[c + 2]);
                        v3 = g * (v3 + biasc[c + 3]);
                        red4(dst + c, v0, v1, v2, v3);
                    }
                }
            }
        }

        e = e2; mt = mt2; nt = nt2; cnt = cnt2; buf = nbuf; have = have2;
    }

    // ---- completion ticket: last CTA resets state for the next replay ----
    if (tid == 0) {
        int d = atomicAdd(&g_done, 1);
        if (d == GRID_CTAS - 1) {
#pragma unroll
            for (int i = 0; i < NEXP; i++) g_cnt[i] = 0;
            atomicExch(&g_widx, 0);
            atomicExch(&g_done, 0);
        }
    }
}

// ------------------- launch -------------------
extern "C" void kernel_launch(void* const* d_in, const int* in_sizes, int n_in,
                              void* d_out, int out_size) {
    const float* x  = (const float*)d_in[0];
    const float* rw = (const float*)d_in[1];
    const float* rb = (const float*)d_in[2];
    const float* ew = (const float*)d_in[3];
    const float* eb = (const float*)d_in[4];

    cudaFuncSetAttribute(gemm_kernel, cudaFuncAttributeMaxDynamicSharedMemorySize,
                         (int)SMEM_TOTAL);

    fused_prep_router<<<FUSED_BLOCKS, 256>>>(x, rw, rb,
                                             (const float4*)ew, (float4*)d_out);  // idx 0
    gemm_kernel<<<GRID_CTAS, 128, SMEM_TOTAL>>>(eb, (float*)d_out);               // idx 1
}